// round 8
// baseline (speedup 1.0000x reference)
#include <cuda_runtime.h>
#include <cstdint>
#include <cstddef>

// ---------------- problem constants ----------------
#define T_STEPS 16384
#define HDIM    512
#define GDIM    1536          // 3*H
#define NCTA    16            // one cluster, all-to-all DSMEM
#define HPC     32            // h elements per CTA
#define RPC     96            // W_hh rows per CTA (3 gates x HPC)
#define NTH     384           // 12 warps; thread = 2 rows x 64 cols

// ---------------- device scratch ----------------
__device__ float g_gi[(size_t)T_STEPS * GDIM];     // input gates (100 MB)

// ---------------- GEMM: gi = x @ W_ih^T + b_ih ----------------
#define BM 128
#define BN 128
#define BK 8

__global__ void __launch_bounds__(256) gemm_gi(
    const float* __restrict__ x, const float* __restrict__ Wih,
    const float* __restrict__ bih) {
    __shared__ __align__(16) float As[BK][BM];
    __shared__ __align__(16) float Bs[BK][BN];
    const int bn  = blockIdx.x;
    const int bm  = blockIdx.y;
    const int tid = threadIdx.x;
    const int tx  = tid & 15;
    const int ty  = tid >> 4;

    const int lrow = tid >> 1;
    const int lseg = (tid & 1) * 4;
    const float* xp = x   + (size_t)(bm * BM + lrow) * HDIM + lseg;
    const float* wp = Wih + (size_t)(bn * BN + lrow) * HDIM + lseg;

    float acc[8][8];
#pragma unroll
    for (int i = 0; i < 8; i++)
#pragma unroll
        for (int j = 0; j < 8; j++) acc[i][j] = 0.f;

    for (int k0 = 0; k0 < HDIM; k0 += BK) {
        float4 av = *(const float4*)(xp + k0);
        float4 bv = *(const float4*)(wp + k0);
        As[lseg + 0][lrow] = av.x; As[lseg + 1][lrow] = av.y;
        As[lseg + 2][lrow] = av.z; As[lseg + 3][lrow] = av.w;
        Bs[lseg + 0][lrow] = bv.x; Bs[lseg + 1][lrow] = bv.y;
        Bs[lseg + 2][lrow] = bv.z; Bs[lseg + 3][lrow] = bv.w;
        __syncthreads();
#pragma unroll
        for (int k = 0; k < BK; k++) {
            float4 a0 = *(const float4*)&As[k][ty * 8];
            float4 a1 = *(const float4*)&As[k][ty * 8 + 4];
            float4 b0 = *(const float4*)&Bs[k][tx * 8];
            float4 b1 = *(const float4*)&Bs[k][tx * 8 + 4];
            float a[8] = {a0.x, a0.y, a0.z, a0.w, a1.x, a1.y, a1.z, a1.w};
            float b[8] = {b0.x, b0.y, b0.z, b0.w, b1.x, b1.y, b1.z, b1.w};
#pragma unroll
            for (int i = 0; i < 8; i++)
#pragma unroll
                for (int j = 0; j < 8; j++)
                    acc[i][j] = fmaf(a[i], b[j], acc[i][j]);
        }
        __syncthreads();
    }
#pragma unroll
    for (int i = 0; i < 8; i++) {
        int row = bm * BM + ty * 8 + i;
        float* gp = &g_gi[(size_t)row * GDIM + bn * BN + tx * 8];
#pragma unroll
        for (int j = 0; j < 8; j++)
            gp[j] = acc[i][j] + bih[bn * BN + tx * 8 + j];
    }
}

// ---------------- helpers ----------------
__device__ __forceinline__ uint32_t smem_u32(const void* p) {
    uint32_t a;
    asm("{ .reg .u64 t; cvta.to.shared.u64 t, %1; cvt.u32.u64 %0, t; }"
        : "=r"(a) : "l"(p));
    return a;
}
__device__ __forceinline__ float f32x2_hsum(unsigned long long a) {
    float lo, hi;
    asm("mov.b64 {%0,%1}, %2;" : "=f"(lo), "=f"(hi) : "l"(a));
    return lo + hi;
}
__device__ __forceinline__ float fast_sigmoid(float x) {
    return __fdividef(1.f, 1.f + __expf(-x));
}
__device__ __forceinline__ float fast_tanh(float x) {
    x = fminf(fmaxf(x, -20.f), 20.f);
    float e = __expf(2.f * x);
    return __fdividef(e - 1.f, e + 1.f);
}
__device__ __forceinline__ unsigned long long pack2(float a, float b) {
    unsigned long long r;
    asm("mov.b64 %0, {%1,%2};" : "=l"(r) : "f"(a), "f"(b));
    return r;
}
__device__ __forceinline__ void mbar_wait_acq_cluster(uint32_t mbar, uint32_t parity) {
    asm volatile(
        "{\n\t.reg .pred P;\n"
        "W%=:\n\t"
        "mbarrier.try_wait.parity.acquire.cluster.shared::cta.b64 P, [%0], %1, 0x989680;\n\t"
        "@!P bra W%=;\n\t}"
        :: "r"(mbar), "r"(parity) : "memory");
}

// ---------------- persistent GRU scan (one 16-CTA cluster) ----------------
__global__ void __launch_bounds__(NTH, 1) __cluster_dims__(NCTA, 1, 1)
gru_scan(const float* __restrict__ Whh, const float* __restrict__ bhh,
         float* __restrict__ out) {
    __shared__ __align__(16) unsigned long long hbuf[2][HDIM / 2]; // packed h pairs
    __shared__ __align__(8)  unsigned long long mbar[2];
    __shared__ float red_s[RPC];
    __shared__ float gi_s[2][RPC];
    __shared__ float bhh_s[RPC];

    const int c   = blockIdx.x;          // cluster rank
    const int tid = threadIdx.x;
    const int w   = tid >> 5;
    const int l   = tid & 31;
    const int rp  = tid >> 3;            // row-pair 0..47
    const int q   = tid & 7;             // lane in row-pair (cols 64q..64q+63)

    // ---- weights: 2 rows x 64 cols per thread = 64 u64 (128 regs) ----
    unsigned long long w0[32], w1[32];
    {
        const int lr0 = 2 * rp, lr1 = 2 * rp + 1;
        const int gR0 = (lr0 / HPC) * HDIM + c * HPC + (lr0 % HPC);
        const int gR1 = (lr1 / HPC) * HDIM + c * HPC + (lr1 % HPC);
        const ulonglong2* p0 = (const ulonglong2*)(Whh + (size_t)gR0 * HDIM + q * 64);
        const ulonglong2* p1 = (const ulonglong2*)(Whh + (size_t)gR1 * HDIM + q * 64);
#pragma unroll
        for (int k = 0; k < 16; k++) {
            ulonglong2 v0 = __ldg(p0 + k); w0[2 * k] = v0.x; w0[2 * k + 1] = v0.y;
            ulonglong2 v1 = __ldg(p1 + k); w1[2 * k] = v1.x; w1[2 * k + 1] = v1.y;
        }
    }

    const int gr2 = (tid / HPC) * HDIM + c * HPC + (tid % HPC);  // for tid<RPC
    if (tid < RPC) {
        bhh_s[tid]   = bhh[gr2];
        gi_s[0][tid] = g_gi[gr2];
    }
    for (int i = tid; i < HDIM / 2; i += NTH) hbuf[0][i] = 0ull;  // h(0) = 0

    const uint32_t mbar_u32 = smem_u32(&mbar[0]);
    const uint32_t hbuf_u32 = smem_u32(&hbuf[0][0]);
    if (tid == 0) {
        asm volatile("mbarrier.init.shared.b64 [%0], %1;" :: "r"(mbar_u32), "r"(NCTA));
        asm volatile("mbarrier.init.shared.b64 [%0], %1;" :: "r"(mbar_u32 + 8), "r"(NCTA));
    }
    __syncthreads();
    asm volatile("barrier.cluster.arrive.aligned;" ::: "memory");
    asm volatile("barrier.cluster.wait.aligned;" ::: "memory");

    unsigned ph0 = 0, ph1 = 0;
    float hprev = 0.f;

    for (int t = 0; t < T_STEPS; ++t) {
        const int b = t & 1;

        // gi(t+1) prefetch — issued before the wait, completes under it
        float gi_pf = 0.f;
        const bool pf = (tid < RPC) && (t + 1 < T_STEPS);
        if (pf) gi_pf = __ldg(&g_gi[(size_t)(t + 1) * GDIM + gr2]);

        if (t > 0) {
            if (b) { mbar_wait_acq_cluster(mbar_u32 + 8, ph1); ph1 ^= 1; }
            else   { mbar_wait_acq_cluster(mbar_u32,     ph0); ph0 ^= 1; }
        }

        // ---- matvec: weights in regs, h from own SMEM (broadcast LDS.128) ----
        const unsigned long long* hv = &hbuf[b][q << 5];   // pairs 32q..32q+31
        unsigned long long a00 = 0ull, a01 = 0ull, a10 = 0ull, a11 = 0ull;
#pragma unroll
        for (int k = 0; k < 16; k++) {
            ulonglong2 h2 = *(const ulonglong2*)(hv + 2 * k);
            asm("fma.rn.f32x2 %0, %1, %2, %0;" : "+l"(a00) : "l"(w0[2 * k]),     "l"(h2.x));
            asm("fma.rn.f32x2 %0, %1, %2, %0;" : "+l"(a01) : "l"(w0[2 * k + 1]), "l"(h2.y));
            asm("fma.rn.f32x2 %0, %1, %2, %0;" : "+l"(a10) : "l"(w1[2 * k]),     "l"(h2.x));
            asm("fma.rn.f32x2 %0, %1, %2, %0;" : "+l"(a11) : "l"(w1[2 * k + 1]), "l"(h2.y));
        }
        float s0 = f32x2_hsum(a00) + f32x2_hsum(a01);
        float s1 = f32x2_hsum(a10) + f32x2_hsum(a11);
#pragma unroll
        for (int off = 4; off; off >>= 1) {
            s0 += __shfl_xor_sync(0xffffffffu, s0, off);
            s1 += __shfl_xor_sync(0xffffffffu, s1, off);
        }
        if (q == 0) { red_s[2 * rp] = s0; red_s[2 * rp + 1] = s1; }
        if (pf) gi_s[b ^ 1][tid] = gi_pf;
        __syncthreads();                       // red_s / gi_s ready

        // ---- gates + DSMEM publish (warp 0, 32 lanes = 32 h values) ----
        if (w == 0) {
            float ghr = red_s[l]           + bhh_s[l];
            float ghz = red_s[HPC + l]     + bhh_s[HPC + l];
            float ghn = red_s[2 * HPC + l] + bhh_s[2 * HPC + l];
            float gir = gi_s[b][l];
            float giz = gi_s[b][HPC + l];
            float gin = gi_s[b][2 * HPC + l];
            float r = fast_sigmoid(gir + ghr);
            float z = fast_sigmoid(giz + ghz);
            float n = fast_tanh(gin + r * ghn);
            float hnew = n + z * (hprev - n);  // (1-z)*n + z*h
            hprev = hnew;
            out[(size_t)t * HDIM + c * HPC + l] = hnew;

            if (t + 1 < T_STEPS) {
                float partner = __shfl_xor_sync(0xffffffffu, hnew, 1);
                unsigned long long pk = pack2(hnew, partner); // even lane: {h_l, h_{l+1}}
                const uint32_t slot = hbuf_u32 +
                    (uint32_t)(((b ^ 1) * (HDIM / 2) + (c * HPC + l) / 2) * 8);
                if ((l & 1) == 0) {
#pragma unroll
                    for (int p = 0; p < NCTA; p++) {
                        uint32_t ra;
                        asm volatile("mapa.shared::cluster.u32 %0, %1, %2;"
                                     : "=r"(ra) : "r"(slot), "r"(p));
                        asm volatile("st.shared::cluster.u64 [%0], %1;"
                                     :: "r"(ra), "l"(pk) : "memory");
                    }
                }
                __syncwarp();
                if (l < NCTA) {
                    uint32_t rm;
                    asm volatile("mapa.shared::cluster.u32 %0, %1, %2;"
                                 : "=r"(rm) : "r"(mbar_u32 + (b ^ 1) * 8), "r"(l));
                    asm volatile(
                        "mbarrier.arrive.release.cluster.shared::cluster.b64 _, [%0];"
                        :: "r"(rm) : "memory");
                }
            }
        }
    }

    asm volatile("barrier.cluster.arrive.aligned;" ::: "memory");
    asm volatile("barrier.cluster.wait.aligned;" ::: "memory");
}

// ---------------- launch ----------------
extern "C" void kernel_launch(void* const* d_in, const int* in_sizes, int n_in,
                              void* d_out, int out_size) {
    const float* x   = (const float*)d_in[0];
    const float* Wih = (const float*)d_in[1];
    const float* Whh = (const float*)d_in[2];
    const float* bih = (const float*)d_in[3];
    const float* bhh = (const float*)d_in[4];
    float* out = (float*)d_out;

    static int attr_done = 0;
    if (!attr_done) {
        cudaFuncSetAttribute(gru_scan,
                             cudaFuncAttributeNonPortableClusterSizeAllowed, 1);
        attr_done = 1;
    }

    dim3 ggrid(GDIM / BN, T_STEPS / BM);   // (12, 128)
    gemm_gi<<<ggrid, 256>>>(x, Wih, bih);
    gru_scan<<<NCTA, NTH>>>(Whh, bhh, out);
}

// round 9
// speedup vs baseline: 2.2229x; 2.2229x over previous
#include <cuda_runtime.h>
#include <cstdint>
#include <cstddef>

// ---------------- problem constants ----------------
#define T_STEPS 16384
#define HDIM    512
#define GDIM    1536          // 3*H
#define NCTA    32
#define HPC     16            // h elements per CTA
#define RPC     48            // W_hh rows per CTA (3 gates x HPC)
#define NTH     384           // 12 warps; 8 lanes per row
#define POLLW   11            // poller / h-stager / gi-prefetch warp
#define PD      8             // gi ring depth

// ---------------- device scratch ----------------
__device__ float    g_gi[(size_t)T_STEPS * GDIM];  // input gates (100 MB)
__device__ float    g_h[2][HDIM];                  // double-buffered hidden state
__device__ unsigned g_cnt;                         // barrier counter

// ---------------- GEMM: gi = x @ W_ih^T + b_ih  (+ scan-state reset) ----
#define BM 128
#define BN 128
#define BK 8

__global__ void __launch_bounds__(256) gemm_gi(
    const float* __restrict__ x, const float* __restrict__ Wih,
    const float* __restrict__ bih) {
    if (blockIdx.x == 0 && blockIdx.y == 0) {
        if (threadIdx.x == 0) g_cnt = 0u;
        for (int i = threadIdx.x; i < 2 * HDIM; i += 256) (&g_h[0][0])[i] = 0.f;
    }

    __shared__ __align__(16) float As[BK][BM];
    __shared__ __align__(16) float Bs[BK][BN];
    const int bn  = blockIdx.x;
    const int bm  = blockIdx.y;
    const int tid = threadIdx.x;
    const int tx  = tid & 15;
    const int ty  = tid >> 4;

    const int lrow = tid >> 1;
    const int lseg = (tid & 1) * 4;
    const float* xp = x   + (size_t)(bm * BM + lrow) * HDIM + lseg;
    const float* wp = Wih + (size_t)(bn * BN + lrow) * HDIM + lseg;

    float acc[8][8];
#pragma unroll
    for (int i = 0; i < 8; i++)
#pragma unroll
        for (int j = 0; j < 8; j++) acc[i][j] = 0.f;

    for (int k0 = 0; k0 < HDIM; k0 += BK) {
        float4 av = *(const float4*)(xp + k0);
        float4 bv = *(const float4*)(wp + k0);
        As[lseg + 0][lrow] = av.x; As[lseg + 1][lrow] = av.y;
        As[lseg + 2][lrow] = av.z; As[lseg + 3][lrow] = av.w;
        Bs[lseg + 0][lrow] = bv.x; Bs[lseg + 1][lrow] = bv.y;
        Bs[lseg + 2][lrow] = bv.z; Bs[lseg + 3][lrow] = bv.w;
        __syncthreads();
#pragma unroll
        for (int k = 0; k < BK; k++) {
            float4 a0 = *(const float4*)&As[k][ty * 8];
            float4 a1 = *(const float4*)&As[k][ty * 8 + 4];
            float4 b0 = *(const float4*)&Bs[k][tx * 8];
            float4 b1 = *(const float4*)&Bs[k][tx * 8 + 4];
            float a[8] = {a0.x, a0.y, a0.z, a0.w, a1.x, a1.y, a1.z, a1.w};
            float b[8] = {b0.x, b0.y, b0.z, b0.w, b1.x, b1.y, b1.z, b1.w};
#pragma unroll
            for (int i = 0; i < 8; i++)
#pragma unroll
                for (int j = 0; j < 8; j++)
                    acc[i][j] = fmaf(a[i], b[j], acc[i][j]);
        }
        __syncthreads();
    }
#pragma unroll
    for (int i = 0; i < 8; i++) {
        int row = bm * BM + ty * 8 + i;
        float* gp = &g_gi[(size_t)row * GDIM + bn * BN + tx * 8];
#pragma unroll
        for (int j = 0; j < 8; j++)
            gp[j] = acc[i][j] + bih[bn * BN + tx * 8 + j];
    }
}

// ---------------- scan helpers ----------------
__device__ __forceinline__ uint32_t smem_u32(const void* p) {
    uint32_t a;
    asm("{ .reg .u64 t; cvta.to.shared.u64 t, %1; cvt.u32.u64 %0, t; }"
        : "=r"(a) : "l"(p));
    return a;
}
__device__ __forceinline__ float f32x2_hsum(unsigned long long a) {
    float lo, hi;
    asm("mov.b64 {%0,%1}, %2;" : "=f"(lo), "=f"(hi) : "l"(a));
    return lo + hi;
}
__device__ __forceinline__ float mufu_tanh(float x) {
    float r;
    asm("tanh.approx.f32 %0, %1;" : "=f"(r) : "f"(x));
    return r;
}
__device__ __forceinline__ float mufu_sigmoid(float x) {
    return fmaf(mufu_tanh(0.5f * x), 0.5f, 0.5f);
}

// ---------------- persistent GRU scan ----------------
__global__ void __launch_bounds__(NTH, 1) gru_scan(
    const float* __restrict__ Whh, const float* __restrict__ bhh,
    float* __restrict__ out) {
    __shared__ __align__(16) float h_s[HDIM];       // staged hidden state
    __shared__ __align__(16) float ring[PD][RPC];   // gi prefetch ring
    __shared__ float red_s[RPC];
    __shared__ float bhh_s[RPC];

    const int c   = blockIdx.x;
    const int tid = threadIdx.x;
    const int wid = tid >> 5;
    const int l   = tid & 31;
    const int lr  = tid >> 3;            // local row 0..47
    const int j   = tid & 7;             // lane within row

    // global row (gate-major: r,z,n blocks of HPC)
    const int gr = (lr / HPC) * HDIM + c * HPC + (lr % HPC);

    // ---- weights resident in registers: 16 x (u64,u64) ----
    unsigned long long wlo[16], whi[16];
    {
        const ulonglong2* wp =
            (const ulonglong2*)(Whh + (size_t)gr * HDIM + j * 4);
#pragma unroll
        for (int s = 0; s < 16; ++s) {
            ulonglong2 wv = __ldg(wp + s * 8);   // stride 128B
            wlo[s] = wv.x; whi[s] = wv.y;
        }
    }

    if (tid < RPC) {
        const int gr2 = (tid / HPC) * HDIM + c * HPC + (tid % HPC);
        bhh_s[tid] = bhh[gr2];
    }

    // ---- gi ring prologue: slots 0..6 (poller warp, lanes 0-11) ----
    const uint32_t ring_u32 = smem_u32(&ring[0][0]);
    if (wid == POLLW) {
#pragma unroll
        for (int p = 0; p < PD - 1; p++) {
            if (l < 12) {
                const float* src = &g_gi[(size_t)p * GDIM +
                                         (l >> 2) * HDIM + c * HPC + (l & 3) * 4];
                uint32_t dst = ring_u32 + (uint32_t)((p * RPC + l * 4) * 4);
                asm volatile("cp.async.cg.shared.global [%0], [%1], 16;"
                             :: "r"(dst), "l"(src));
            }
            asm volatile("cp.async.commit_group;");
        }
        asm volatile("cp.async.wait_group 0;");
    }

    const int hbase = c * HPC;
    float hprev = 0.f;
    __syncthreads();

    for (int t = 0; t < T_STEPS; ++t) {
        const int par = t & 1;

        // ---- poller warp: poll -> gi prefetch -> stage h into SMEM ----
        if (wid == POLLW) {
            if (t > 0) {
                const unsigned tgt = 32u * (unsigned)t;
                unsigned f;
                do {
                    asm volatile("ld.acquire.gpu.global.u32 %0, [%1];"
                                 : "=r"(f) : "l"(&g_cnt));
                } while (f < tgt);
            }
            // prefetch gi(t+7) into ring slot (t+7)&7 (slot was consumed at t-1)
            {
                int tp = t + PD - 1;
                if (tp >= T_STEPS) tp = T_STEPS - 1;
                if (l < 12) {
                    const float* src = &g_gi[(size_t)tp * GDIM +
                                             (l >> 2) * HDIM + c * HPC + (l & 3) * 4];
                    uint32_t dst = ring_u32 +
                        (uint32_t)(((tp & (PD - 1)) * RPC + l * 4) * 4);
                    asm volatile("cp.async.cg.shared.global [%0], [%1], 16;"
                                 :: "r"(dst), "l"(src));
                }
                asm volatile("cp.async.commit_group;");
                asm volatile("cp.async.wait_group 6;");
            }
            // stage h(t): 2KB global -> SMEM (coalesced, L2-fresh after acquire)
            const float* hg = g_h[par];
#pragma unroll
            for (int k = 0; k < 4; k++) {
                float4 v;
                asm volatile("ld.global.cg.v4.f32 {%0,%1,%2,%3}, [%4];"
                             : "=f"(v.x), "=f"(v.y), "=f"(v.z), "=f"(v.w)
                             : "l"(hg + (l + 32 * k) * 4));
                *(float4*)(h_s + (l + 32 * k) * 4) = v;
            }
        }
        __syncthreads();                 // bar A: h_s + ring slot t ready

        // ---- matvec: weights from regs, h from SMEM (broadcast LDS.128) ----
        const float* hv = h_s + j * 4;
        unsigned long long a0 = 0ull, a1 = 0ull, a2 = 0ull, a3 = 0ull;
#pragma unroll
        for (int s = 0; s < 16; s += 2) {
            ulonglong2 p0 = *(const ulonglong2*)(hv + s * 32);
            ulonglong2 p1 = *(const ulonglong2*)(hv + (s + 1) * 32);
            asm("fma.rn.f32x2 %0, %1, %2, %0;" : "+l"(a0) : "l"(wlo[s]),     "l"(p0.x));
            asm("fma.rn.f32x2 %0, %1, %2, %0;" : "+l"(a1) : "l"(whi[s]),     "l"(p0.y));
            asm("fma.rn.f32x2 %0, %1, %2, %0;" : "+l"(a2) : "l"(wlo[s + 1]), "l"(p1.x));
            asm("fma.rn.f32x2 %0, %1, %2, %0;" : "+l"(a3) : "l"(whi[s + 1]), "l"(p1.y));
        }
        float acc = (f32x2_hsum(a0) + f32x2_hsum(a1)) +
                    (f32x2_hsum(a2) + f32x2_hsum(a3));
        acc += __shfl_xor_sync(0xffffffffu, acc, 4);
        acc += __shfl_xor_sync(0xffffffffu, acc, 2);
        acc += __shfl_xor_sync(0xffffffffu, acc, 1);
        if (j == 0) red_s[lr] = acc;
        __syncthreads();                 // bar B: red_s ready

        // ---- gate math + publish (warp 0, lanes 0..15) ----
        if (wid == 0) {
            float hnew = 0.f;
            if (l < HPC) {
                const float* gi = &ring[t & (PD - 1)][0];
                float r = mufu_sigmoid(gi[l]           + red_s[l]           + bhh_s[l]);
                float z = mufu_sigmoid(gi[HPC + l]     + red_s[HPC + l]     + bhh_s[HPC + l]);
                float n = mufu_tanh  (gi[2 * HPC + l] + fmaf(r, red_s[2 * HPC + l] + bhh_s[2 * HPC + l], 0.f));
                hnew = n + z * (hprev - n);          // (1-z)*n + z*h
                hprev = hnew;
                asm volatile("st.global.cg.f32 [%0], %1;"
                             :: "l"(&g_h[par ^ 1][hbase + l]), "f"(hnew) : "memory");
            }
            __syncwarp();
            if (l == 0) {
                asm volatile("red.release.gpu.global.add.u32 [%0], %1;"
                             :: "l"(&g_cnt), "r"(1u) : "memory");
            }
            if (l < HPC)                 // off the serial path
                out[(size_t)t * HDIM + hbase + l] = hnew;
        }
    }
}

// ---------------- launch ----------------
extern "C" void kernel_launch(void* const* d_in, const int* in_sizes, int n_in,
                              void* d_out, int out_size) {
    const float* x   = (const float*)d_in[0];
    const float* Wih = (const float*)d_in[1];
    const float* Whh = (const float*)d_in[2];
    const float* bih = (const float*)d_in[3];
    const float* bhh = (const float*)d_in[4];
    float* out = (float*)d_out;

    dim3 ggrid(GDIM / BN, T_STEPS / BM);   // (12, 128)
    gemm_gi<<<ggrid, 256>>>(x, Wih, bih);
    gru_scan<<<NCTA, NTH>>>(Whh, bhh, out);
}

// round 10
// speedup vs baseline: 2.8518x; 1.2829x over previous
#include <cuda_runtime.h>
#include <cstdint>
#include <cstddef>

// ---------------- problem constants ----------------
#define T_STEPS 16384
#define HDIM    512
#define GDIM    1536          // 3*H
#define NCTA    32
#define HPC     16            // h elements per CTA
#define RPC     48            // W_hh rows per CTA (3 gates x HPC)
#define NTH     384           // 12 warps; 8 lanes per row
#define POLLW   11            // poller / h-stager / gi-prefetch warp
#define PD      8             // gi ring depth

// ---------------- device scratch ----------------
__device__ float              g_gi[(size_t)T_STEPS * GDIM]; // gi + folded biases
__device__ unsigned long long g_ht[2][HDIM];                // {tag:hi32, h:lo32}

// ---------------- GEMM: gi = x @ W_ih^T + bih (+bhh for r,z gates) ----------
#define BM 128
#define BN 128
#define BK 8

__global__ void __launch_bounds__(256) gemm_gi(
    const float* __restrict__ x, const float* __restrict__ Wih,
    const float* __restrict__ bih, const float* __restrict__ bhh) {
    // block (0,0) resets tagged h buffers: tag=0,val=0 (buf0 = valid h(0))
    if (blockIdx.x == 0 && blockIdx.y == 0) {
        unsigned long long* p = &g_ht[0][0];
        for (int i = threadIdx.x; i < 2 * HDIM; i += 256) p[i] = 0ULL;
    }

    __shared__ __align__(16) float As[BK][BM];
    __shared__ __align__(16) float Bs[BK][BN];
    const int bn  = blockIdx.x;
    const int bm  = blockIdx.y;
    const int tid = threadIdx.x;
    const int tx  = tid & 15;
    const int ty  = tid >> 4;

    const int lrow = tid >> 1;
    const int lseg = (tid & 1) * 4;
    const float* xp = x   + (size_t)(bm * BM + lrow) * HDIM + lseg;
    const float* wp = Wih + (size_t)(bn * BN + lrow) * HDIM + lseg;

    float acc[8][8];
#pragma unroll
    for (int i = 0; i < 8; i++)
#pragma unroll
        for (int j = 0; j < 8; j++) acc[i][j] = 0.f;

    for (int k0 = 0; k0 < HDIM; k0 += BK) {
        float4 av = *(const float4*)(xp + k0);
        float4 bv = *(const float4*)(wp + k0);
        As[lseg + 0][lrow] = av.x; As[lseg + 1][lrow] = av.y;
        As[lseg + 2][lrow] = av.z; As[lseg + 3][lrow] = av.w;
        Bs[lseg + 0][lrow] = bv.x; Bs[lseg + 1][lrow] = bv.y;
        Bs[lseg + 2][lrow] = bv.z; Bs[lseg + 3][lrow] = bv.w;
        __syncthreads();
#pragma unroll
        for (int k = 0; k < BK; k++) {
            float4 a0 = *(const float4*)&As[k][ty * 8];
            float4 a1 = *(const float4*)&As[k][ty * 8 + 4];
            float4 b0 = *(const float4*)&Bs[k][tx * 8];
            float4 b1 = *(const float4*)&Bs[k][tx * 8 + 4];
            float a[8] = {a0.x, a0.y, a0.z, a0.w, a1.x, a1.y, a1.z, a1.w};
            float b[8] = {b0.x, b0.y, b0.z, b0.w, b1.x, b1.y, b1.z, b1.w};
#pragma unroll
            for (int i = 0; i < 8; i++)
#pragma unroll
                for (int j = 0; j < 8; j++)
                    acc[i][j] = fmaf(a[i], b[j], acc[i][j]);
        }
        __syncthreads();
    }
#pragma unroll
    for (int i = 0; i < 8; i++) {
        int row = bm * BM + ty * 8 + i;
        float* gp = &g_gi[(size_t)row * GDIM + bn * BN + tx * 8];
#pragma unroll
        for (int j = 0; j < 8; j++) {
            int col = bn * BN + tx * 8 + j;
            float b = bih[col];
            if (col < 2 * HDIM) b += bhh[col];   // fold bhh for r,z gates only
            gp[j] = acc[i][j] + b;
        }
    }
}

// ---------------- scan helpers ----------------
__device__ __forceinline__ uint32_t smem_u32(const void* p) {
    uint32_t a;
    asm("{ .reg .u64 t; cvta.to.shared.u64 t, %1; cvt.u32.u64 %0, t; }"
        : "=r"(a) : "l"(p));
    return a;
}
__device__ __forceinline__ float f32x2_hsum(unsigned long long a) {
    float lo, hi;
    asm("mov.b64 {%0,%1}, %2;" : "=f"(lo), "=f"(hi) : "l"(a));
    return lo + hi;
}
__device__ __forceinline__ float mufu_tanh(float x) {
    float r;
    asm("tanh.approx.f32 %0, %1;" : "=f"(r) : "f"(x));
    return r;
}
__device__ __forceinline__ float mufu_sigmoid(float x) {
    return fmaf(mufu_tanh(0.5f * x), 0.5f, 0.5f);
}

// ---------------- persistent GRU scan ----------------
__global__ void __launch_bounds__(NTH, 1) gru_scan(
    const float* __restrict__ Whh, const float* __restrict__ bhh,
    float* __restrict__ out) {
    __shared__ __align__(16) float h_s[HDIM];       // staged hidden state
    __shared__ __align__(16) float ring[PD][RPC];   // gi prefetch ring
    __shared__ float red_s[RPC];
    __shared__ float bhhn_s[HPC];                   // bhh for n gate only

    const int c   = blockIdx.x;
    const int tid = threadIdx.x;
    const int wid = tid >> 5;
    const int l   = tid & 31;
    const int lr  = tid >> 3;            // local row 0..47
    const int j   = tid & 7;             // lane within row

    // global row (gate-major: r,z,n blocks of HPC)
    const int gr = (lr / HPC) * HDIM + c * HPC + (lr % HPC);

    // ---- weights resident in registers: 16 x (u64,u64) ----
    unsigned long long wlo[16], whi[16];
    {
        const ulonglong2* wp =
            (const ulonglong2*)(Whh + (size_t)gr * HDIM + j * 4);
#pragma unroll
        for (int s = 0; s < 16; ++s) {
            ulonglong2 wv = __ldg(wp + s * 8);   // stride 128B
            wlo[s] = wv.x; whi[s] = wv.y;
        }
    }

    if (tid < HPC) bhhn_s[tid] = bhh[2 * HDIM + c * HPC + tid];

    // ---- gi ring prologue: slots 0..6 (poller warp, lanes 0-11) ----
    const uint32_t ring_u32 = smem_u32(&ring[0][0]);
    if (wid == POLLW) {
#pragma unroll
        for (int p = 0; p < PD - 1; p++) {
            if (l < 12) {
                const float* src = &g_gi[(size_t)p * GDIM +
                                         (l >> 2) * HDIM + c * HPC + (l & 3) * 4];
                uint32_t dst = ring_u32 + (uint32_t)((p * RPC + l * 4) * 4);
                asm volatile("cp.async.cg.shared.global [%0], [%1], 16;"
                             :: "r"(dst), "l"(src));
            }
            asm volatile("cp.async.commit_group;");
        }
        asm volatile("cp.async.wait_group 0;");
    }

    const int hbase = c * HPC;
    float hprev = 0.f;
    __syncthreads();

    for (int t = 0; t < T_STEPS; ++t) {
        const int par = t & 1;

        // ---- poller warp: tagged-data poll+capture, gi prefetch, stage ----
        if (wid == POLLW) {
            const unsigned long long* hb = &g_ht[par][0];
            const unsigned long long thr = (unsigned long long)(unsigned)t << 32;
            unsigned long long q[16];
            for (;;) {
#pragma unroll
                for (int i = 0; i < 16; i++)
                    asm volatile("ld.relaxed.gpu.global.u64 %0, [%1];"
                                 : "=l"(q[i]) : "l"(hb + l + 32 * i));
                bool ok = true;
#pragma unroll
                for (int i = 0; i < 16; i++) ok &= (q[i] >= thr);
                if (__all_sync(0xffffffffu, ok)) break;
            }
            // gi(t+7) into ring slot (t+7)&7 (safe: poll passed => slot consumed)
            {
                int tp = t + PD - 1;
                if (tp >= T_STEPS) tp = T_STEPS - 1;
                if (l < 12) {
                    const float* src = &g_gi[(size_t)tp * GDIM +
                                             (l >> 2) * HDIM + c * HPC + (l & 3) * 4];
                    uint32_t dst = ring_u32 +
                        (uint32_t)(((tp & (PD - 1)) * RPC + l * 4) * 4);
                    asm volatile("cp.async.cg.shared.global [%0], [%1], 16;"
                                 :: "r"(dst), "l"(src));
                }
                asm volatile("cp.async.commit_group;");
                asm volatile("cp.async.wait_group 6;");
            }
            // stage h(t): strip tags
#pragma unroll
            for (int i = 0; i < 16; i++)
                h_s[l + 32 * i] = __uint_as_float((unsigned)q[i]);
        }
        __syncthreads();                 // bar A: h_s + ring slot t ready

        // ---- matvec: weights from regs, h from SMEM (broadcast LDS.128) ----
        const float* hv = h_s + j * 4;
        unsigned long long a0 = 0ull, a1 = 0ull, a2 = 0ull, a3 = 0ull;
#pragma unroll
        for (int s = 0; s < 16; s += 2) {
            ulonglong2 p0 = *(const ulonglong2*)(hv + s * 32);
            ulonglong2 p1 = *(const ulonglong2*)(hv + (s + 1) * 32);
            asm("fma.rn.f32x2 %0, %1, %2, %0;" : "+l"(a0) : "l"(wlo[s]),     "l"(p0.x));
            asm("fma.rn.f32x2 %0, %1, %2, %0;" : "+l"(a1) : "l"(whi[s]),     "l"(p0.y));
            asm("fma.rn.f32x2 %0, %1, %2, %0;" : "+l"(a2) : "l"(wlo[s + 1]), "l"(p1.x));
            asm("fma.rn.f32x2 %0, %1, %2, %0;" : "+l"(a3) : "l"(whi[s + 1]), "l"(p1.y));
        }
        float acc = (f32x2_hsum(a0) + f32x2_hsum(a1)) +
                    (f32x2_hsum(a2) + f32x2_hsum(a3));
        acc += __shfl_xor_sync(0xffffffffu, acc, 4);
        acc += __shfl_xor_sync(0xffffffffu, acc, 2);
        acc += __shfl_xor_sync(0xffffffffu, acc, 1);
        if (j == 0) red_s[lr] = acc;
        __syncthreads();                 // bar B: red_s ready

        // ---- gate math + tagged publish (warp 0, lanes 0..15) ----
        if (wid == 0) {
            float hnew = 0.f;
            if (l < HPC) {
                const float* gi = &ring[t & (PD - 1)][0];
                float r = mufu_sigmoid(gi[l]       + red_s[l]);
                float z = mufu_sigmoid(gi[HPC + l] + red_s[HPC + l]);
                float n = mufu_tanh(fmaf(r, red_s[2 * HPC + l] + bhhn_s[l],
                                         gi[2 * HPC + l]));
                hnew = n + z * (hprev - n);          // (1-z)*n + z*h
                hprev = hnew;
                unsigned long long pk =
                    (unsigned long long)__float_as_uint(hnew) |
                    ((unsigned long long)(unsigned)(t + 1) << 32);
                asm volatile("st.relaxed.gpu.global.u64 [%0], %1;"
                             :: "l"(&g_ht[par ^ 1][hbase + l]), "l"(pk) : "memory");
                out[(size_t)t * HDIM + hbase + l] = hnew;  // off the serial path
            }
        }
    }
}

// ---------------- launch ----------------
extern "C" void kernel_launch(void* const* d_in, const int* in_sizes, int n_in,
                              void* d_out, int out_size) {
    const float* x   = (const float*)d_in[0];
    const float* Wih = (const float*)d_in[1];
    const float* Whh = (const float*)d_in[2];
    const float* bih = (const float*)d_in[3];
    const float* bhh = (const float*)d_in[4];
    float* out = (float*)d_out;

    dim3 ggrid(GDIM / BN, T_STEPS / BM);   // (12, 128)
    gemm_gi<<<ggrid, 256>>>(x, Wih, bih, bhh);
    gru_scan<<<NCTA, NTH>>>(Whh, bhh, out);
}